// round 1
// baseline (speedup 1.0000x reference)
#include <cuda_runtime.h>
#include <cstdint>

// Packed fp32x2 FMA (Blackwell): d = a*b + c per 32-bit lane.
#define FMA2(d, a, b, c) \
    asm("fma.rn.f32x2 %0, %1, %2, %3;" : "=l"(d) : "l"(a), "l"(b), "l"(c))

// Combined weight: Wc_t[k][ch] = sum_e gcn_w[ch][e] * conv_w[e][k],
// k = c*4 + u*2 + v (flattened conv_w trailing dims). Stored k-major so a
// float2 load at [k][2*cp] yields the (ch, ch+1) pair a lane needs.
__device__ float g_wc[12 * 192];

__global__ void wc_kernel(const float* __restrict__ conv_w,
                          const float* __restrict__ gcn_w) {
    int k  = blockIdx.x;    // 0..11
    int ch = threadIdx.x;   // 0..191
    float s = 0.f;
#pragma unroll 8
    for (int e = 0; e < 192; e++)
        s += gcn_w[ch * 192 + e] * conv_w[e * 12 + k];
    g_wc[k * 192 + ch] = s;
}

// Grid: 256x256 patch nodes. deg = 1 + #neighbors (self-loop).
__device__ __forceinline__ float dinv_of(int gi, int gj) {
    int deg = 1 + (gi > 0) + (gi < 255) + (gj > 0) + (gj < 255);
    return rsqrtf((float)deg);
}

__global__ __launch_bounds__(384, 2)
void fused_kernel(const float* __restrict__ x,
                  const float* __restrict__ bias,
                  float* __restrict__ out) {
    // sp[halo_node][k]: dinv_src * patch value. 18x18 nodes, stride 13 (pad).
    __shared__ float  sp[324 * 13];
    // acc2[node][k]: dinv_dst * stencil-sum, pre-splatted to float2. stride 13.
    __shared__ float2 acc2[256 * 13];

    const int t  = threadIdx.x;
    const int b  = blockIdx.z;
    const int ti = blockIdx.y;
    const int tj = blockIdx.x;

    // ---- per-lane fixed channel pair for phase 3; load weights into regs ----
    const int ng = t / 96;          // node sub-group 0..3
    const int cp = t % 96;          // channel pair 0..95
    const int ch = 2 * cp;
    unsigned long long w[12];
#pragma unroll
    for (int k = 0; k < 12; k++)
        w[k] = *reinterpret_cast<const unsigned long long*>(&g_wc[k * 192 + ch]);
    const unsigned long long bb =
        *reinterpret_cast<const unsigned long long*>(&bias[ch]);

    // ---- phase 1: stage dinv_src * patch for 18x18 halo ----
    if (t < 324) {
        const int li = t / 18, lj = t % 18;
        const int gi = ti * 16 - 1 + li;
        const int gj = tj * 16 - 1 + lj;
        float vals[12];
#pragma unroll
        for (int k = 0; k < 12; k++) vals[k] = 0.f;
        float dv = 0.f;
        if (gi >= 0 && gi < 256 && gj >= 0 && gj < 256) {
            dv = dinv_of(gi, gj);
#pragma unroll
            for (int c = 0; c < 3; c++) {
#pragma unroll
                for (int u = 0; u < 2; u++) {
                    const size_t off =
                        (((size_t)b * 3 + c) * 512 + (size_t)(gi * 2 + u)) * 512
                        + (size_t)(gj * 2);
                    const float2 v = *reinterpret_cast<const float2*>(&x[off]);
                    vals[c * 4 + u * 2 + 0] = v.x;
                    vals[c * 4 + u * 2 + 1] = v.y;
                }
            }
        }
#pragma unroll
        for (int k = 0; k < 12; k++) sp[t * 13 + k] = dv * vals[k];
    }
    __syncthreads();

    // ---- phase 2: 5-point stencil in 12-dim patch space ----
    if (t < 256) {
        const int li = t / 16, lj = t % 16;
        const int gi = ti * 16 + li;
        const int gj = tj * 16 + lj;
        const float dv = dinv_of(gi, gj);
        const int c0 = ((li + 1) * 18 + (lj + 1)) * 13;
#pragma unroll
        for (int k = 0; k < 12; k++) {
            float a = sp[c0 + k]
                    + sp[c0 - 18 * 13 + k]   // up
                    + sp[c0 + 18 * 13 + k]   // down
                    + sp[c0 - 13 + k]        // left
                    + sp[c0 + 13 + k];       // right
            a *= dv;
            acc2[t * 13 + k] = make_float2(a, a);
        }
    }
    __syncthreads();

    // ---- phase 3: per-node [1x12] @ Wc[12x192] + bias, packed fp32x2 ----
    const size_t outbase = (size_t)b * 65536 * 192;
    const int tibase = (ti * 16) * 256 + tj * 16;

#pragma unroll 2
    for (int i = 0; i < 64; i++) {
        const int node = i * 4 + ng;            // 0..255
        const int li = node / 16, lj = node % 16;
        const size_t ncol = (size_t)(tibase + li * 256 + lj);
        unsigned long long accum = bb;
        const float2* ap = &acc2[node * 13];
#pragma unroll
        for (int k = 0; k < 12; k++) {
            const unsigned long long av =
                *reinterpret_cast<const unsigned long long*>(ap + k);
            FMA2(accum, av, w[k], accum);
        }
        *reinterpret_cast<unsigned long long*>(
            &out[outbase + ncol * 192 + (size_t)ch]) = accum;
    }
}

extern "C" void kernel_launch(void* const* d_in, const int* in_sizes, int n_in,
                              void* d_out, int out_size) {
    const float* x      = (const float*)d_in[0];   // [4,3,512,512]
    const float* conv_w = (const float*)d_in[1];   // [192,3,2,2]
    const float* gcn_w  = (const float*)d_in[2];   // [192,192]
    const float* gcn_b  = (const float*)d_in[3];   // [192]
    float* out = (float*)d_out;                    // [4,65536,192]

    wc_kernel<<<12, 192>>>(conv_w, gcn_w);

    dim3 grid(16, 16, 4);   // (tile_j, tile_i, batch)
    fused_kernel<<<grid, 384>>>(x, gcn_b, out);
}

// round 2
// speedup vs baseline: 1.4451x; 1.4451x over previous
#include <cuda_runtime.h>
#include <cstdint>

typedef unsigned long long ull_t;

// Packed fp32x2 FMA (Blackwell): d = a*b + c per 32-bit lane.
#define FMA2(d, a, b, c) \
    asm("fma.rn.f32x2 %0, %1, %2, %3;" : "=l"(d) : "l"(a), "l"(b), "l"(c))

// Combined weight: Wc[k][ch] = sum_e gcn_w[ch][e] * conv_w[e][k],
// k = c*4 + u*2 + v. Stored k-major: float2 at [k][2*cp] = (ch, ch+1) pair.
__device__ float g_wc[12 * 192];

// One warp per output element (2304 warps): lane-strided dot + shuffle reduce.
__global__ void wc_kernel(const float* __restrict__ conv_w,
                          const float* __restrict__ gcn_w) {
    const int w    = (blockIdx.x * blockDim.x + threadIdx.x) >> 5;  // 0..2303
    const int lane = threadIdx.x & 31;
    if (w >= 2304) return;
    const int k  = w % 12;
    const int ch = w / 12;
    float s = 0.f;
#pragma unroll
    for (int j = 0; j < 6; j++) {
        const int e = lane + 32 * j;
        s += gcn_w[ch * 192 + e] * conv_w[e * 12 + k];
    }
#pragma unroll
    for (int off = 16; off > 0; off >>= 1)
        s += __shfl_xor_sync(0xffffffffu, s, off);
    if (lane == 0) g_wc[k * 192 + ch] = s;
}

// 256x256 patch grid; deg = 1 + #neighbors (self-loop).
__device__ __forceinline__ float dinv_of(int gi, int gj) {
    int deg = 1 + (gi > 0) + (gi < 255) + (gj > 0) + (gj < 255);
    return rsqrtf((float)deg);
}

// Tile: 8 rows x 16 cols of nodes, halo 10x18.
__global__ __launch_bounds__(384, 2)
void fused_kernel(const float* __restrict__ x,
                  const float* __restrict__ bias,
                  float* __restrict__ out) {
    // sp[halo][k]: dinv_src * patch, 180 halo nodes, 12 floats (48B, f4-aligned)
    __shared__ float  sp[180 * 12];
    // accq[node][j]: splatted float2 pairs; 6 float4 used + 1 pad (112B/node)
    __shared__ float4 accq[128 * 7];

    const int t  = threadIdx.x;
    const int b  = blockIdx.z;
    const int ti = blockIdx.y;   // 0..31 (8-row bands)
    const int tj = blockIdx.x;   // 0..15 (16-col bands)

    // ---- per-lane channel pair + weights in registers ----
    const int ng = t / 96;       // node sub-group 0..3 (2 rows each)
    const int cp = t % 96;
    const int ch = 2 * cp;
    ull_t w[12];
#pragma unroll
    for (int k = 0; k < 12; k++)
        w[k] = *reinterpret_cast<const ull_t*>(&g_wc[k * 192 + ch]);
    const ull_t bb = *reinterpret_cast<const ull_t*>(&bias[ch]);

    // ---- phase 1: stage dinv_src * patch for 10x18 halo ----
    if (t < 180) {
        const int li = t / 18, lj = t % 18;
        const int gi = ti * 8 - 1 + li;
        const int gj = tj * 16 - 1 + lj;
        float v[12];
#pragma unroll
        for (int k = 0; k < 12; k++) v[k] = 0.f;
        float dv = 0.f;
        if (gi >= 0 && gi < 256 && gj >= 0 && gj < 256) {
            dv = dinv_of(gi, gj);
#pragma unroll
            for (int c = 0; c < 3; c++) {
#pragma unroll
                for (int u = 0; u < 2; u++) {
                    const size_t off =
                        (((size_t)b * 3 + c) * 512 + (size_t)(gi * 2 + u)) * 512
                        + (size_t)(gj * 2);
                    const float2 p = *reinterpret_cast<const float2*>(&x[off]);
                    v[c * 4 + u * 2 + 0] = p.x;
                    v[c * 4 + u * 2 + 1] = p.y;
                }
            }
        }
        float4* dst = reinterpret_cast<float4*>(&sp[t * 12]);
        dst[0] = make_float4(dv * v[0], dv * v[1], dv * v[2],  dv * v[3]);
        dst[1] = make_float4(dv * v[4], dv * v[5], dv * v[6],  dv * v[7]);
        dst[2] = make_float4(dv * v[8], dv * v[9], dv * v[10], dv * v[11]);
    }
    __syncthreads();

    // ---- phase 2: 5-point stencil in 12-dim patch space, splat to pairs ----
    if (t < 128) {
        const int li = t / 16, lj = t % 16;
        const float dv = dinv_of(ti * 8 + li, tj * 16 + lj);
        const int c0 = ((li + 1) * 18 + (lj + 1)) * 12;
        float a[12];
#pragma unroll
        for (int q = 0; q < 3; q++) {
            const float4 vc = *reinterpret_cast<const float4*>(&sp[c0 + 4 * q]);
            const float4 vu = *reinterpret_cast<const float4*>(&sp[c0 - 18 * 12 + 4 * q]);
            const float4 vd = *reinterpret_cast<const float4*>(&sp[c0 + 18 * 12 + 4 * q]);
            const float4 vl = *reinterpret_cast<const float4*>(&sp[c0 - 12 + 4 * q]);
            const float4 vr = *reinterpret_cast<const float4*>(&sp[c0 + 12 + 4 * q]);
            a[4 * q + 0] = dv * (vc.x + vu.x + vd.x + vl.x + vr.x);
            a[4 * q + 1] = dv * (vc.y + vu.y + vd.y + vl.y + vr.y);
            a[4 * q + 2] = dv * (vc.z + vu.z + vd.z + vl.z + vr.z);
            a[4 * q + 3] = dv * (vc.w + vu.w + vd.w + vl.w + vr.w);
        }
        float4* dst = &accq[t * 7];
#pragma unroll
        for (int j = 0; j < 6; j++)
            dst[j] = make_float4(a[2 * j], a[2 * j], a[2 * j + 1], a[2 * j + 1]);
    }
    __syncthreads();

    // ---- phase 3: [1x12] @ Wc[12x192] + bias, fp32x2, LDS.128 acc loads ----
    // Node block for this group: rows [ng*2, ng*2+2), 16 cols; node = ng*32+i.
    float* op = out + (size_t)b * 65536 * 192
              + (size_t)((ti * 8 + ng * 2) * 256 + tj * 16) * 192 + (size_t)ch;
    const float4* aq = &accq[(ng * 32) * 7];

#pragma unroll 4
    for (int i = 0; i < 32; i++) {
        ull_t acc = bb;
        const ulonglong2* ap =
            reinterpret_cast<const ulonglong2*>(aq + (size_t)i * 7);
#pragma unroll
        for (int j = 0; j < 6; j++) {
            const ulonglong2 v = ap[j];           // LDS.128: two splatted pairs
            FMA2(acc, v.x, w[2 * j],     acc);
            FMA2(acc, v.y, w[2 * j + 1], acc);
        }
        *reinterpret_cast<ull_t*>(op + (size_t)(((i >> 4) * 256) + (i & 15)) * 192) = acc;
    }
}

extern "C" void kernel_launch(void* const* d_in, const int* in_sizes, int n_in,
                              void* d_out, int out_size) {
    const float* x      = (const float*)d_in[0];   // [4,3,512,512]
    const float* conv_w = (const float*)d_in[1];   // [192,3,2,2]
    const float* gcn_w  = (const float*)d_in[2];   // [192,192]
    const float* gcn_b  = (const float*)d_in[3];   // [192]
    float* out = (float*)d_out;                    // [4,65536,192]

    wc_kernel<<<288, 256>>>(conv_w, gcn_w);        // 2304 warps, 1 per output

    dim3 grid(16, 32, 4);   // (tile_j, tile_i, batch)
    fused_kernel<<<grid, 384>>>(x, gcn_b, out);
}

// round 3
// speedup vs baseline: 1.8142x; 1.2554x over previous
#include <cuda_runtime.h>
#include <cstdint>

typedef unsigned long long ull_t;

// Packed fp32x2 FMA (Blackwell): d = a*b + c per 32-bit lane.
#define FMA2(d, a, b, c) \
    asm("fma.rn.f32x2 %0, %1, %2, %3;" : "=l"(d) : "l"(a), "l"(b), "l"(c))

// Splat one fp32 into both halves of a 64-bit reg pair.
#define SPLAT(s, f) \
    asm("mov.b64 %0, {%1, %1};" : "=l"(s) : "f"(f))

// Combined weight: Wc[k][ch] = sum_e gcn_w[ch][e] * conv_w[e][k],
// k = c*4 + u*2 + v. Stored k-major: float2 at [k][ch] = (ch, ch+1) pair.
__device__ float g_wc[12 * 192];

// One warp per output element (2304 warps): lane-strided dot + shuffle reduce.
__global__ void wc_kernel(const float* __restrict__ conv_w,
                          const float* __restrict__ gcn_w) {
    const int w    = (blockIdx.x * blockDim.x + threadIdx.x) >> 5;  // 0..2303
    const int lane = threadIdx.x & 31;
    if (w >= 2304) return;
    const int k  = w % 12;
    const int ch = w / 12;
    float s = 0.f;
#pragma unroll
    for (int j = 0; j < 6; j++) {
        const int e = lane + 32 * j;
        s += gcn_w[ch * 192 + e] * conv_w[e * 12 + k];
    }
#pragma unroll
    for (int off = 16; off > 0; off >>= 1)
        s += __shfl_xor_sync(0xffffffffu, s, off);
    if (lane == 0) g_wc[k * 192 + ch] = s;
}

// 256x256 patch grid; deg = 1 + #neighbors (self-loop).
__device__ __forceinline__ float dinv_of(int gi, int gj) {
    int deg = 1 + (gi > 0) + (gi < 255) + (gj > 0) + (gj < 255);
    return rsqrtf((float)deg);
}

// Tile: 8 rows x 16 cols of nodes (128), halo 10x18 (180). 256 threads.
__global__ __launch_bounds__(256, 2)
void fused_kernel(const float* __restrict__ x,
                  const float* __restrict__ bias,
                  float* __restrict__ out) {
    // sp[halo][k]: dinv_src * patch value; 12 floats/node (48B, f4-aligned)
    __shared__ float sp[180 * 12];
    // accs[node][k]: dinv_dst * stencil sum; 12 plain floats/node
    __shared__ float accs[128 * 12];

    const int t    = threadIdx.x;
    const int lane = t & 31;
    const int wid  = t >> 5;     // 0..7 : warp == node-row within tile
    const int b    = blockIdx.z;
    const int ti   = blockIdx.y; // 0..31 (8-row bands)
    const int tj   = blockIdx.x; // 0..15 (16-col bands)

    // ---- per-lane: 3 channel pairs (ch, ch+64, ch+128); weights in regs ----
    const int ch = 2 * lane;
    ull_t w0[12], w1[12], w2[12];
#pragma unroll
    for (int k = 0; k < 12; k++) {
        const float* row = &g_wc[k * 192 + ch];
        w0[k] = *reinterpret_cast<const ull_t*>(row);
        w1[k] = *reinterpret_cast<const ull_t*>(row + 64);
        w2[k] = *reinterpret_cast<const ull_t*>(row + 128);
    }
    const ull_t bb0 = *reinterpret_cast<const ull_t*>(&bias[ch]);
    const ull_t bb1 = *reinterpret_cast<const ull_t*>(&bias[ch + 64]);
    const ull_t bb2 = *reinterpret_cast<const ull_t*>(&bias[ch + 128]);

    // ---- phase 1: stage dinv_src * patch for 10x18 halo ----
    if (t < 180) {
        const int li = t / 18, lj = t % 18;
        const int gi = ti * 8 - 1 + li;
        const int gj = tj * 16 - 1 + lj;
        float v[12];
#pragma unroll
        for (int k = 0; k < 12; k++) v[k] = 0.f;
        float dv = 0.f;
        if (gi >= 0 && gi < 256 && gj >= 0 && gj < 256) {
            dv = dinv_of(gi, gj);
#pragma unroll
            for (int c = 0; c < 3; c++) {
#pragma unroll
                for (int u = 0; u < 2; u++) {
                    const size_t off =
                        (((size_t)b * 3 + c) * 512 + (size_t)(gi * 2 + u)) * 512
                        + (size_t)(gj * 2);
                    const float2 p = *reinterpret_cast<const float2*>(&x[off]);
                    v[c * 4 + u * 2 + 0] = p.x;
                    v[c * 4 + u * 2 + 1] = p.y;
                }
            }
        }
        float4* dst = reinterpret_cast<float4*>(&sp[t * 12]);
        dst[0] = make_float4(dv * v[0], dv * v[1], dv * v[2],  dv * v[3]);
        dst[1] = make_float4(dv * v[4], dv * v[5], dv * v[6],  dv * v[7]);
        dst[2] = make_float4(dv * v[8], dv * v[9], dv * v[10], dv * v[11]);
    }
    __syncthreads();

    // ---- phase 2: 5-point stencil in 12-dim patch space ----
    if (t < 128) {
        const int li = t / 16, lj = t % 16;
        const float dv = dinv_of(ti * 8 + li, tj * 16 + lj);
        const int c0 = ((li + 1) * 18 + (lj + 1)) * 12;
        float4* dst = reinterpret_cast<float4*>(&accs[t * 12]);
#pragma unroll
        for (int q = 0; q < 3; q++) {
            const float4 vc = *reinterpret_cast<const float4*>(&sp[c0 + 4 * q]);
            const float4 vu = *reinterpret_cast<const float4*>(&sp[c0 - 18 * 12 + 4 * q]);
            const float4 vd = *reinterpret_cast<const float4*>(&sp[c0 + 18 * 12 + 4 * q]);
            const float4 vl = *reinterpret_cast<const float4*>(&sp[c0 - 12 + 4 * q]);
            const float4 vr = *reinterpret_cast<const float4*>(&sp[c0 + 12 + 4 * q]);
            dst[q] = make_float4(dv * (vc.x + vu.x + vd.x + vl.x + vr.x),
                                 dv * (vc.y + vu.y + vd.y + vl.y + vr.y),
                                 dv * (vc.z + vu.z + vd.z + vl.z + vr.z),
                                 dv * (vc.w + vu.w + vd.w + vl.w + vr.w));
        }
    }
    __syncthreads();

    // ---- phase 3: one warp per node-row; lane owns ch, ch+64, ch+128 ----
    // Warp wid handles nodes n = wid*16 + lj (tile row wid, cols 0..15).
    float* op = out + (size_t)b * 65536 * 192
              + (size_t)((ti * 8 + wid) * 256 + tj * 16) * 192 + (size_t)ch;
    const float* ac = &accs[(wid * 16) * 12];

#pragma unroll 2
    for (int i = 0; i < 16; i++) {
        const float4 a0 = *reinterpret_cast<const float4*>(ac + i * 12);      // LDS.128 bcast
        const float4 a1 = *reinterpret_cast<const float4*>(ac + i * 12 + 4);
        const float4 a2 = *reinterpret_cast<const float4*>(ac + i * 12 + 8);
        const float av[12] = {a0.x, a0.y, a0.z, a0.w,
                              a1.x, a1.y, a1.z, a1.w,
                              a2.x, a2.y, a2.z, a2.w};
        ull_t acc0 = bb0, acc1 = bb1, acc2 = bb2;
#pragma unroll
        for (int k = 0; k < 12; k++) {
            ull_t s;
            SPLAT(s, av[k]);
            FMA2(acc0, s, w0[k], acc0);
            FMA2(acc1, s, w1[k], acc1);
            FMA2(acc2, s, w2[k], acc2);
        }
        float* o = op + (size_t)i * 192;
        *reinterpret_cast<ull_t*>(o)       = acc0;
        *reinterpret_cast<ull_t*>(o + 64)  = acc1;
        *reinterpret_cast<ull_t*>(o + 128) = acc2;
    }
}

extern "C" void kernel_launch(void* const* d_in, const int* in_sizes, int n_in,
                              void* d_out, int out_size) {
    const float* x      = (const float*)d_in[0];   // [4,3,512,512]
    const float* conv_w = (const float*)d_in[1];   // [192,3,2,2]
    const float* gcn_w  = (const float*)d_in[2];   // [192,192]
    const float* gcn_b  = (const float*)d_in[3];   // [192]
    float* out = (float*)d_out;                    // [4,65536,192]

    wc_kernel<<<288, 256>>>(conv_w, gcn_w);        // 2304 warps, 1 per output

    dim3 grid(16, 32, 4);   // (tile_j, tile_i, batch)
    fused_kernel<<<grid, 256>>>(x, gcn_b, out);
}

// round 4
// speedup vs baseline: 1.8396x; 1.0140x over previous
#include <cuda_runtime.h>
#include <cstdint>

typedef unsigned long long ull_t;

// Packed fp32x2 FMA (Blackwell): d = a*b + c per 32-bit lane.
#define FMA2(d, a, b, c) \
    asm("fma.rn.f32x2 %0, %1, %2, %3;" : "=l"(d) : "l"(a), "l"(b), "l"(c))

// Splat one fp32 into both halves of a 64-bit reg pair.
#define SPLAT(s, f) \
    asm("mov.b64 %0, {%1, %1};" : "=l"(s) : "f"(f))

// Combined weight: Wc[k][ch] = sum_e gcn_w[ch][e] * conv_w[e][k],
// k = c*4 + u*2 + v. Stored k-major: float2 at [k][ch] = (ch, ch+1) pair.
__device__ float g_wc[12 * 192];

// One warp per output element (2304 warps): lane-strided dot + shuffle reduce.
__global__ void wc_kernel(const float* __restrict__ conv_w,
                          const float* __restrict__ gcn_w) {
    const int w    = (blockIdx.x * blockDim.x + threadIdx.x) >> 5;  // 0..2303
    const int lane = threadIdx.x & 31;
    if (w >= 2304) return;
    const int k  = w % 12;
    const int ch = w / 12;
    float s = 0.f;
#pragma unroll
    for (int j = 0; j < 6; j++) {
        const int e = lane + 32 * j;
        s += gcn_w[ch * 192 + e] * conv_w[e * 12 + k];
    }
#pragma unroll
    for (int off = 16; off > 0; off >>= 1)
        s += __shfl_xor_sync(0xffffffffu, s, off);
    if (lane == 0) g_wc[k * 192 + ch] = s;
}

// 256x256 patch grid; deg = 1 + #neighbors (self-loop).
__device__ __forceinline__ float dinv_of(int gi, int gj) {
    int deg = 1 + (gi > 0) + (gi < 255) + (gj > 0) + (gj < 255);
    return rsqrtf((float)deg);
}

// Tile: 8 rows x 16 cols of nodes (128), halo 10x18 (180). 384 threads.
// Phase 3: 12 warps = 3 channel-groups x 4 row-pairs; 24 weight regs/lane.
__global__ __launch_bounds__(384, 3)
void fused_kernel(const float* __restrict__ x,
                  const float* __restrict__ bias,
                  float* __restrict__ out) {
    // sp[halo][k]: dinv_src * patch value; 12 floats/node (48B, f4-aligned)
    __shared__ float sp[180 * 12];
    // accs[node][k]: dinv_dst * stencil sum; 12 plain floats/node
    __shared__ float accs[128 * 12];

    const int t    = threadIdx.x;
    const int lane = t & 31;
    const int wid  = t >> 5;     // 0..11
    const int b    = blockIdx.z;
    const int ti   = blockIdx.y; // 0..31 (8-row bands)
    const int tj   = blockIdx.x; // 0..15 (16-col bands)

    // ---- per-lane: ONE channel pair within this warp's group ----
    const int g  = wid >> 2;             // channel group 0..2
    const int r  = wid & 3;              // row-pair 0..3 (rows 2r, 2r+1)
    const int ch = 64 * g + 2 * lane;
    ull_t w[12];
#pragma unroll
    for (int k = 0; k < 12; k++)
        w[k] = *reinterpret_cast<const ull_t*>(&g_wc[k * 192 + ch]);
    const ull_t bb = *reinterpret_cast<const ull_t*>(&bias[ch]);

    // ---- phase 1: stage dinv_src * patch for 10x18 halo; 2 threads/node ----
    if (t < 360) {
        const int hn = t >> 1;           // halo node 0..179
        const int u  = t & 1;            // pixel row within patch
        const int li = hn / 18, lj = hn % 18;
        const int gi = ti * 8 - 1 + li;
        const int gj = tj * 16 - 1 + lj;
        float2 v[3];
#pragma unroll
        for (int c = 0; c < 3; c++) v[c] = make_float2(0.f, 0.f);
        float dv = 0.f;
        if (gi >= 0 && gi < 256 && gj >= 0 && gj < 256) {
            dv = dinv_of(gi, gj);
#pragma unroll
            for (int c = 0; c < 3; c++) {
                const size_t off =
                    (((size_t)b * 3 + c) * 512 + (size_t)(gi * 2 + u)) * 512
                    + (size_t)(gj * 2);
                v[c] = *reinterpret_cast<const float2*>(&x[off]);
            }
        }
#pragma unroll
        for (int c = 0; c < 3; c++) {
            float2* dst =
                reinterpret_cast<float2*>(&sp[hn * 12 + c * 4 + u * 2]);
            *dst = make_float2(dv * v[c].x, dv * v[c].y);
        }
    }
    __syncthreads();

    // ---- phase 2: 5-point stencil; all 384 threads (node, quad q) ----
    {
        const int node = t & 127;
        const int q    = t >> 7;         // 0..2
        const int li = node / 16, lj = node % 16;
        const float dv = dinv_of(ti * 8 + li, tj * 16 + lj);
        const int c0 = ((li + 1) * 18 + (lj + 1)) * 12 + 4 * q;
        const float4 vc = *reinterpret_cast<const float4*>(&sp[c0]);
        const float4 vu = *reinterpret_cast<const float4*>(&sp[c0 - 18 * 12]);
        const float4 vd = *reinterpret_cast<const float4*>(&sp[c0 + 18 * 12]);
        const float4 vl = *reinterpret_cast<const float4*>(&sp[c0 - 12]);
        const float4 vr = *reinterpret_cast<const float4*>(&sp[c0 + 12]);
        *reinterpret_cast<float4*>(&accs[node * 12 + 4 * q]) =
            make_float4(dv * (vc.x + vu.x + vd.x + vl.x + vr.x),
                        dv * (vc.y + vu.y + vd.y + vl.y + vr.y),
                        dv * (vc.z + vu.z + vd.z + vl.z + vr.z),
                        dv * (vc.w + vu.w + vd.w + vl.w + vr.w));
    }
    __syncthreads();

    // ---- phase 3: warp = (group g, row-pair r); 32 nodes, 64 ch each ----
    const float* ac = &accs[(r * 32) * 12];
    float* op = out + (size_t)b * 65536 * 192
              + (size_t)((ti * 8 + 2 * r) * 256 + tj * 16) * 192 + (size_t)ch;

#pragma unroll 4
    for (int i = 0; i < 32; i++) {
        const float4 a0 = *reinterpret_cast<const float4*>(ac + i * 12);
        const float4 a1 = *reinterpret_cast<const float4*>(ac + i * 12 + 4);
        const float4 a2 = *reinterpret_cast<const float4*>(ac + i * 12 + 8);
        const float av[12] = {a0.x, a0.y, a0.z, a0.w,
                              a1.x, a1.y, a1.z, a1.w,
                              a2.x, a2.y, a2.z, a2.w};
        ull_t acc = bb;
#pragma unroll
        for (int k = 0; k < 12; k++) {
            ull_t s;
            SPLAT(s, av[k]);
            FMA2(acc, s, w[k], acc);
        }
        *reinterpret_cast<ull_t*>(
            op + (size_t)(((i >> 4) * 256) + (i & 15)) * 192) = acc;
    }
}

extern "C" void kernel_launch(void* const* d_in, const int* in_sizes, int n_in,
                              void* d_out, int out_size) {
    const float* x      = (const float*)d_in[0];   // [4,3,512,512]
    const float* conv_w = (const float*)d_in[1];   // [192,3,2,2]
    const float* gcn_w  = (const float*)d_in[2];   // [192,192]
    const float* gcn_b  = (const float*)d_in[3];   // [192]
    float* out = (float*)d_out;                    // [4,65536,192]

    wc_kernel<<<288, 256>>>(conv_w, gcn_w);        // 2304 warps, 1 per output

    dim3 grid(16, 32, 4);   // (tile_j, tile_i, batch)
    fused_kernel<<<grid, 384>>>(x, gcn_b, out);
}

// round 5
// speedup vs baseline: 1.9172x; 1.0422x over previous
#include <cuda_runtime.h>
#include <cstdint>

typedef unsigned long long ull_t;

// Packed fp32x2 FMA (Blackwell): d = a*b + c per 32-bit lane.
#define FMA2(d, a, b, c) \
    asm("fma.rn.f32x2 %0, %1, %2, %3;" : "=l"(d) : "l"(a), "l"(b), "l"(c))

// Splat one fp32 into both halves of a 64-bit reg pair.
#define SPLAT(s, f) \
    asm("mov.b64 %0, {%1, %1};" : "=l"(s) : "f"(f))

// Combined weight: Wc[k][ch] = sum_e gcn_w[ch][e] * conv_w[e][k],
// k = c*4 + u*2 + v. Stored k-major: float2 at [k][ch] = (ch, ch+1) pair.
__device__ float g_wc[12 * 192];

// One warp per output element (2304 warps): lane-strided dot + shuffle reduce.
__global__ void wc_kernel(const float* __restrict__ conv_w,
                          const float* __restrict__ gcn_w) {
    const int w    = (blockIdx.x * blockDim.x + threadIdx.x) >> 5;  // 0..2303
    const int lane = threadIdx.x & 31;
    if (w >= 2304) return;
    const int k  = w % 12;
    const int ch = w / 12;
    float s = 0.f;
#pragma unroll
    for (int j = 0; j < 6; j++) {
        const int e = lane + 32 * j;
        s += gcn_w[ch * 192 + e] * conv_w[e * 12 + k];
    }
#pragma unroll
    for (int off = 16; off > 0; off >>= 1)
        s += __shfl_xor_sync(0xffffffffu, s, off);
    if (lane == 0) g_wc[k * 192 + ch] = s;
}

// 256x256 patch grid; deg = 1 + #neighbors (self-loop).
__device__ __forceinline__ float dinv_of(int gi, int gj) {
    int deg = 1 + (gi > 0) + (gi < 255) + (gj > 0) + (gj < 255);
    return rsqrtf((float)deg);
}

// Tile: 16x16 nodes (256), halo 18x18 (324). 384 threads, 3 CTAs/SM.
// Phase 3: 12 warps = 3 channel-groups x 4 row-quads; 24 weight regs/lane.
__global__ __launch_bounds__(384, 3)
void fused_kernel(const float* __restrict__ x,
                  const float* __restrict__ bias,
                  float* __restrict__ out) {
    // sp[halo][k]: dinv_src * patch value; 12 floats/node
    __shared__ float sp[324 * 12];
    // accs[node][k]: dinv_dst * stencil sum; 12 floats/node
    __shared__ float accs[256 * 12];

    const int t    = threadIdx.x;
    const int lane = t & 31;
    const int wid  = t >> 5;     // 0..11
    const int b    = blockIdx.z;
    const int ti   = blockIdx.y; // 0..15
    const int tj   = blockIdx.x; // 0..15

    // ---- phase 1: stage dinv_src * patch for 18x18 halo (648 tasks) ----
#pragma unroll
    for (int task = t; task < 648; task += 384) {
        const int hn = task >> 1;        // halo node 0..323
        const int u  = task & 1;         // pixel row within patch
        const int li = hn / 18, lj = hn % 18;
        const int gi = ti * 16 - 1 + li;
        const int gj = tj * 16 - 1 + lj;
        float2 v[3];
#pragma unroll
        for (int c = 0; c < 3; c++) v[c] = make_float2(0.f, 0.f);
        float dv = 0.f;
        if (gi >= 0 && gi < 256 && gj >= 0 && gj < 256) {
            dv = dinv_of(gi, gj);
#pragma unroll
            for (int c = 0; c < 3; c++) {
                const size_t off =
                    (((size_t)b * 3 + c) * 512 + (size_t)(gi * 2 + u)) * 512
                    + (size_t)(gj * 2);
                v[c] = *reinterpret_cast<const float2*>(&x[off]);
            }
        }
#pragma unroll
        for (int c = 0; c < 3; c++) {
            float2* dst =
                reinterpret_cast<float2*>(&sp[hn * 12 + c * 4 + u * 2]);
            *dst = make_float2(dv * v[c].x, dv * v[c].y);
        }
    }

    // ---- wait for wc_kernel (PDL); then load weights into registers ----
    cudaGridDependencySynchronize();

    const int g  = wid >> 2;             // channel group 0..2
    const int r  = wid & 3;              // row-quad 0..3 (rows 4r..4r+3)
    const int ch = 64 * g + 2 * lane;
    ull_t w[12];
#pragma unroll
    for (int k = 0; k < 12; k++)
        w[k] = *reinterpret_cast<const ull_t*>(&g_wc[k * 192 + ch]);
    const ull_t bb = *reinterpret_cast<const ull_t*>(&bias[ch]);

    __syncthreads();

    // ---- phase 2: 5-point stencil; 768 tasks (node, quad q) ----
#pragma unroll
    for (int task = t; task < 768; task += 384) {
        const int node = task & 255;
        const int q    = task >> 8;      // 0..2
        const int li = node >> 4, lj = node & 15;
        const float dv = dinv_of(ti * 16 + li, tj * 16 + lj);
        const int c0 = ((li + 1) * 18 + (lj + 1)) * 12 + 4 * q;
        const float4 vc = *reinterpret_cast<const float4*>(&sp[c0]);
        const float4 vu = *reinterpret_cast<const float4*>(&sp[c0 - 18 * 12]);
        const float4 vd = *reinterpret_cast<const float4*>(&sp[c0 + 18 * 12]);
        const float4 vl = *reinterpret_cast<const float4*>(&sp[c0 - 12]);
        const float4 vr = *reinterpret_cast<const float4*>(&sp[c0 + 12]);
        *reinterpret_cast<float4*>(&accs[node * 12 + 4 * q]) =
            make_float4(dv * (vc.x + vu.x + vd.x + vl.x + vr.x),
                        dv * (vc.y + vu.y + vd.y + vl.y + vr.y),
                        dv * (vc.z + vu.z + vd.z + vl.z + vr.z),
                        dv * (vc.w + vu.w + vd.w + vl.w + vr.w));
    }
    __syncthreads();

    // ---- phase 3: warp = (group g, row-quad r); 64 nodes, 64 ch each ----
    const float* ac = &accs[(r * 64) * 12];
    float* op = out + (size_t)b * 65536 * 192
              + (size_t)((ti * 16 + 4 * r) * 256 + tj * 16) * 192 + (size_t)ch;

#pragma unroll
    for (int ii = 0; ii < 4; ii++) {
        const float* arow = ac + ii * 16 * 12;
        float* orow = op + (size_t)ii * 256 * 192;
#pragma unroll 4
        for (int j = 0; j < 16; j++) {
            const float4 a0 = *reinterpret_cast<const float4*>(arow + j * 12);
            const float4 a1 = *reinterpret_cast<const float4*>(arow + j * 12 + 4);
            const float4 a2 = *reinterpret_cast<const float4*>(arow + j * 12 + 8);
            const float av[12] = {a0.x, a0.y, a0.z, a0.w,
                                  a1.x, a1.y, a1.z, a1.w,
                                  a2.x, a2.y, a2.z, a2.w};
            ull_t acc = bb;
#pragma unroll
            for (int k = 0; k < 12; k++) {
                ull_t s;
                SPLAT(s, av[k]);
                FMA2(acc, s, w[k], acc);
            }
            *reinterpret_cast<ull_t*>(orow + (size_t)j * 192) = acc;
        }
    }
}

extern "C" void kernel_launch(void* const* d_in, const int* in_sizes, int n_in,
                              void* d_out, int out_size) {
    const float* x      = (const float*)d_in[0];   // [4,3,512,512]
    const float* conv_w = (const float*)d_in[1];   // [192,3,2,2]
    const float* gcn_w  = (const float*)d_in[2];   // [192,192]
    const float* gcn_b  = (const float*)d_in[3];   // [192]
    float* out = (float*)d_out;                    // [4,65536,192]

    wc_kernel<<<288, 256>>>(conv_w, gcn_w);        // 2304 warps, 1 per output

    // PDL: fused starts while wc runs; gridDependencySynchronize() gates g_wc.
    cudaLaunchConfig_t cfg = {};
    cfg.gridDim  = dim3(16, 16, 4);   // (tile_j, tile_i, batch)
    cfg.blockDim = dim3(384, 1, 1);
    cfg.dynamicSmemBytes = 0;
    cfg.stream = 0;
    cudaLaunchAttribute attr[1];
    attr[0].id = cudaLaunchAttributeProgrammaticStreamSerialization;
    attr[0].val.programmaticStreamSerializationAllowed = 1;
    cfg.attrs = attr;
    cfg.numAttrs = 1;
    cudaError_t e = cudaLaunchKernelEx(&cfg, fused_kernel, x, gcn_b,
                                       (float*)d_out);
    if (e != cudaSuccess) {
        // Fallback: plain stream-ordered launch (still correct).
        dim3 grid(16, 16, 4);
        fused_kernel<<<grid, 384>>>(x, gcn_b, (float*)d_out);
    }
}